// round 1
// baseline (speedup 1.0000x reference)
#include <cuda_runtime.h>
#include <cuda_bf16.h>
#include <math_constants.h>

// Problem constants
#define DIMC     384
#define NHEADS   12
#define HD       32
#define NTOK     49          // tokens per window
#define NWIN     4096        // windows
#define MROWS    (NWIN * NTOK)        // 200704
#define QKV_N    (3 * DIMC)           // 1152

// Scratch (device globals — no allocation allowed)
__device__ float g_qkv[(size_t)MROWS * QKV_N];   // [B*N, 1152]
__device__ float g_att[(size_t)MROWS * DIMC];    // [B*N, 384] attention output (head-merged)

// ---------------------------------------------------------------------------
// SGEMM: C[M,N] = A[M,K] @ B[K,N] + bias[N]
// BM=BN=64, BK=16, 256 threads, 4x4 per thread. Assumes M%64==0, N%64==0, K%16==0.
// ---------------------------------------------------------------------------
__global__ void __launch_bounds__(256)
sgemm_bias(const float* __restrict__ A, const float* __restrict__ B,
           const float* __restrict__ bias, float* __restrict__ C,
           int M, int N, int K)
{
    __shared__ float As[16][64];   // [k][m]
    __shared__ float Bs[16][64];   // [k][n]

    const int bm = blockIdx.y * 64;
    const int bn = blockIdx.x * 64;
    const int tid = threadIdx.x;
    const int tx = tid & 15;       // 0..15 -> n
    const int ty = tid >> 4;       // 0..15 -> m

    // Global-load mapping
    const int arow = tid >> 2;     // 0..63
    const int ak4  = tid & 3;      // 0..3  (k float4)
    const int brow = tid >> 4;     // 0..15 (k)
    const int bc4  = tid & 15;     // 0..15 (n float4)

    float acc[4][4] = {};

    for (int kt = 0; kt < K; kt += 16) {
        float4 a = *(const float4*)&A[(size_t)(bm + arow) * K + kt + ak4 * 4];
        As[ak4 * 4 + 0][arow] = a.x;
        As[ak4 * 4 + 1][arow] = a.y;
        As[ak4 * 4 + 2][arow] = a.z;
        As[ak4 * 4 + 3][arow] = a.w;
        *(float4*)&Bs[brow][bc4 * 4] =
            *(const float4*)&B[(size_t)(kt + brow) * N + bn + bc4 * 4];
        __syncthreads();

        #pragma unroll
        for (int k = 0; k < 16; k++) {
            float4 ra = *(const float4*)&As[k][ty * 4];
            float4 rb = *(const float4*)&Bs[k][tx * 4];
            float a0[4] = {ra.x, ra.y, ra.z, ra.w};
            float b0[4] = {rb.x, rb.y, rb.z, rb.w};
            #pragma unroll
            for (int i = 0; i < 4; i++)
                #pragma unroll
                for (int j = 0; j < 4; j++)
                    acc[i][j] = fmaf(a0[i], b0[j], acc[i][j]);
        }
        __syncthreads();
    }

    #pragma unroll
    for (int i = 0; i < 4; i++) {
        const size_t row = (size_t)(bm + ty * 4 + i);
        #pragma unroll
        for (int j = 0; j < 4; j++) {
            const int col = bn + tx * 4 + j;
            C[row * N + col] = acc[i][j] + bias[col];
        }
    }
}

// ---------------------------------------------------------------------------
// Window attention: one block per (window, head).
// qkv layout: [(b*49+n)*1152 + which*384 + h*32 + d]
// writes g_att[(b*49+n)*384 + h*32 + d]
// ---------------------------------------------------------------------------
__global__ void __launch_bounds__(256)
win_attn(const float* __restrict__ qkv, const float* __restrict__ bias_table,
         const int* __restrict__ rpi, float* __restrict__ out)
{
    const int b = blockIdx.x;
    const int h = blockIdx.y;
    const int tid = threadIdx.x;

    __shared__ float qs[NTOK][HD + 1];
    __shared__ float ks[NTOK][HD + 1];
    __shared__ float vs[NTOK][HD + 1];
    __shared__ float at[NTOK][NTOK + 1];

    const float scale = 0.17677669529663687f;  // 32^-0.5

    // Load q (pre-scaled), k, v
    for (int idx = tid; idx < NTOK * HD; idx += 256) {
        const int n = idx >> 5, d = idx & 31;
        const size_t base = ((size_t)b * NTOK + n) * QKV_N + h * HD + d;
        qs[n][d] = qkv[base] * scale;
        ks[n][d] = qkv[base + DIMC];
        vs[n][d] = qkv[base + 2 * DIMC];
    }
    __syncthreads();

    // Scores + relative-position bias
    for (int idx = tid; idx < NTOK * NTOK; idx += 256) {
        const int n = idx / NTOK, m = idx - n * NTOK;
        float s = 0.f;
        #pragma unroll
        for (int d = 0; d < HD; d++) s = fmaf(qs[n][d], ks[m][d], s);
        s += bias_table[rpi[idx] * NHEADS + h];
        at[n][m] = s;
    }
    __syncthreads();

    // Softmax: one warp per row
    const int warp = tid >> 5, lane = tid & 31;
    for (int n = warp; n < NTOK; n += 8) {
        float v1 = at[n][lane];
        float v2 = (lane < NTOK - 32) ? at[n][lane + 32] : -CUDART_INF_F;
        float mx = fmaxf(v1, v2);
        #pragma unroll
        for (int o = 16; o; o >>= 1) mx = fmaxf(mx, __shfl_xor_sync(0xFFFFFFFFu, mx, o));
        float e1 = __expf(v1 - mx);
        float e2 = (lane < NTOK - 32) ? __expf(v2 - mx) : 0.f;
        float sm = e1 + e2;
        #pragma unroll
        for (int o = 16; o; o >>= 1) sm += __shfl_xor_sync(0xFFFFFFFFu, sm, o);
        const float inv = __frcp_rn(sm);
        at[n][lane] = e1 * inv;
        if (lane < NTOK - 32) at[n][lane + 32] = e2 * inv;
    }
    __syncthreads();

    // out = attn @ v
    for (int idx = tid; idx < NTOK * HD; idx += 256) {
        const int n = idx >> 5, d = idx & 31;
        float s = 0.f;
        #pragma unroll
        for (int m = 0; m < NTOK; m++) s = fmaf(at[n][m], vs[m][d], s);
        out[((size_t)b * NTOK + n) * DIMC + h * HD + d] = s;
    }
}

// ---------------------------------------------------------------------------
extern "C" void kernel_launch(void* const* d_in, const int* in_sizes, int n_in,
                              void* d_out, int out_size)
{
    const float* x          = (const float*)d_in[0];
    const float* qkv_w      = (const float*)d_in[1];
    const float* qkv_b      = (const float*)d_in[2];
    const float* proj_w     = (const float*)d_in[3];
    const float* proj_b     = (const float*)d_in[4];
    const float* bias_table = (const float*)d_in[5];
    const int*   rpi        = (const int*)d_in[6];
    float* out = (float*)d_out;

    float* qkv = nullptr;
    float* att = nullptr;
    cudaGetSymbolAddress((void**)&qkv, g_qkv);
    cudaGetSymbolAddress((void**)&att, g_att);

    // 1) QKV GEMM: [200704, 384] x [384, 1152]
    {
        dim3 grid(QKV_N / 64, MROWS / 64);
        sgemm_bias<<<grid, 256>>>(x, qkv_w, qkv_b, qkv, MROWS, QKV_N, DIMC);
    }

    // 2) Window attention
    {
        dim3 grid(NWIN, NHEADS);
        win_attn<<<grid, 256>>>(qkv, bias_table, rpi, att);
    }

    // 3) Proj GEMM: [200704, 384] x [384, 384]
    {
        dim3 grid(DIMC / 64, MROWS / 64);
        sgemm_bias<<<grid, 256>>>(att, proj_w, proj_b, out, MROWS, DIMC, DIMC);
    }
}

// round 2
// speedup vs baseline: 1.7658x; 1.7658x over previous
#include <cuda_runtime.h>
#include <cuda_bf16.h>
#include <math_constants.h>

// Problem constants
#define DIMC     384
#define NHEADS   12
#define HD       32
#define NTOK     49
#define NWIN     4096
#define MROWS    (NWIN * NTOK)   // 200704
#define QKV_N    (3 * DIMC)      // 1152

// Scratch (device globals — no allocation allowed)
__device__ float g_qkv[(size_t)MROWS * QKV_N];
__device__ float g_att[(size_t)MROWS * DIMC];

// ---------------------------------------------------------------------------
// Tensor-core GEMM (bf16 split x3): C[M,N] = A[M,K] @ B[K,N] + bias[N]
// BM=128, BN=128, BK=32, 256 threads (8 warps: 2(m) x 4(n)), warp tile 64x32.
// Each fp32 operand is split a = hi(bf16) + lo(bf16); products hh+hl+lh give
// ~2^-16 relative accuracy while running on the HMMA pipe.
// ---------------------------------------------------------------------------
#define AST 40    // A smem row stride (bf16 elems), pad for ldmatrix banks
#define BST 136   // B smem row stride (bf16 elems)

__device__ __forceinline__ void ldsm_x4(unsigned* r, const void* p) {
    unsigned a = (unsigned)__cvta_generic_to_shared(p);
    asm volatile("ldmatrix.sync.aligned.m8n8.x4.shared.b16 {%0,%1,%2,%3}, [%4];"
        : "=r"(r[0]), "=r"(r[1]), "=r"(r[2]), "=r"(r[3]) : "r"(a));
}
__device__ __forceinline__ void ldsm_x4_t(unsigned* r, const void* p) {
    unsigned a = (unsigned)__cvta_generic_to_shared(p);
    asm volatile("ldmatrix.sync.aligned.m8n8.x4.trans.shared.b16 {%0,%1,%2,%3}, [%4];"
        : "=r"(r[0]), "=r"(r[1]), "=r"(r[2]), "=r"(r[3]) : "r"(a));
}
__device__ __forceinline__ void mma_bf16(float* d, const unsigned* a, const unsigned* b) {
    asm volatile(
        "mma.sync.aligned.m16n8k16.row.col.f32.bf16.bf16.f32 "
        "{%0,%1,%2,%3}, {%4,%5,%6,%7}, {%8,%9}, {%0,%1,%2,%3};"
        : "+f"(d[0]), "+f"(d[1]), "+f"(d[2]), "+f"(d[3])
        : "r"(a[0]), "r"(a[1]), "r"(a[2]), "r"(a[3]), "r"(b[0]), "r"(b[1]));
}

__device__ __forceinline__ void split2(float x0, float x1,
                                       __nv_bfloat162& h, __nv_bfloat162& l) {
    __nv_bfloat16 h0 = __float2bfloat16(x0);
    __nv_bfloat16 h1 = __float2bfloat16(x1);
    __nv_bfloat16 l0 = __float2bfloat16(x0 - __bfloat162float(h0));
    __nv_bfloat16 l1 = __float2bfloat16(x1 - __bfloat162float(h1));
    h = __nv_bfloat162(h0, h1);
    l = __nv_bfloat162(l0, l1);
}

__global__ void __launch_bounds__(256, 1)
gemm_bf16x3(const float* __restrict__ A, const float* __restrict__ B,
            const float* __restrict__ bias, float* __restrict__ C,
            int M, int N, int K)
{
    __shared__ __nv_bfloat16 sAh[128 * AST];
    __shared__ __nv_bfloat16 sAl[128 * AST];
    __shared__ __nv_bfloat16 sBh[32 * BST];
    __shared__ __nv_bfloat16 sBl[32 * BST];

    const int bm = blockIdx.y * 128;
    const int bn = blockIdx.x * 128;
    const int tid  = threadIdx.x;
    const int warp = tid >> 5;
    const int lane = tid & 31;
    const int wm = (warp >> 2) * 64;   // warp m offset (0/64)
    const int wn = (warp & 3)  * 32;   // warp n offset (0/32/64/96)

    // global-load mappings
    const int arow = tid >> 3;         // 0..31 (base row, + {0,32,64,96})
    const int ac   = (tid & 7) * 4;    // col (float4)
    const int brow = tid >> 5;         // 0..7 (base row, + {0,8,16,24})
    const int bc   = (tid & 31) * 4;   // col (float4)

    float acc[4][4][4] = {};

    for (int kt = 0; kt < K; kt += 32) {
        // Load + split A tile 128x32
        #pragma unroll
        for (int rr = 0; rr < 4; rr++) {
            const int r = arow + rr * 32;
            float4 a = *(const float4*)&A[(size_t)(bm + r) * K + kt + ac];
            __nv_bfloat162 h0, l0, h1, l1;
            split2(a.x, a.y, h0, l0);
            split2(a.z, a.w, h1, l1);
            __nv_bfloat162* ph = (__nv_bfloat162*)&sAh[r * AST + ac];
            __nv_bfloat162* pl = (__nv_bfloat162*)&sAl[r * AST + ac];
            ph[0] = h0; ph[1] = h1;
            pl[0] = l0; pl[1] = l1;
        }
        // Load + split B tile 32x128
        #pragma unroll
        for (int rr = 0; rr < 4; rr++) {
            const int r = brow + rr * 8;
            float4 b = *(const float4*)&B[(size_t)(kt + r) * N + bn + bc];
            __nv_bfloat162 h0, l0, h1, l1;
            split2(b.x, b.y, h0, l0);
            split2(b.z, b.w, h1, l1);
            __nv_bfloat162* ph = (__nv_bfloat162*)&sBh[r * BST + bc];
            __nv_bfloat162* pl = (__nv_bfloat162*)&sBl[r * BST + bc];
            ph[0] = h0; ph[1] = h1;
            pl[0] = l0; pl[1] = l1;
        }
        __syncthreads();

        #pragma unroll
        for (int ks = 0; ks < 32; ks += 16) {
            unsigned ah[4][4], al[4][4];
            unsigned bh[2][4], bl[2][4];
            const int ar = (lane & 15);
            const int akc = ks + ((lane >> 4) << 3);
            #pragma unroll
            for (int mi = 0; mi < 4; mi++) {
                const int row = wm + mi * 16 + ar;
                ldsm_x4(ah[mi], &sAh[row * AST + akc]);
                ldsm_x4(al[mi], &sAl[row * AST + akc]);
            }
            const int bkr = ks + (lane & 15);
            #pragma unroll
            for (int nb = 0; nb < 2; nb++) {
                const int col = wn + nb * 16 + ((lane >> 4) << 3);
                ldsm_x4_t(bh[nb], &sBh[bkr * BST + col]);
                ldsm_x4_t(bl[nb], &sBl[bkr * BST + col]);
            }
            #pragma unroll
            for (int mi = 0; mi < 4; mi++) {
                #pragma unroll
                for (int ni = 0; ni < 4; ni++) {
                    const unsigned* ph = &bh[ni >> 1][(ni & 1) * 2];
                    const unsigned* pl = &bl[ni >> 1][(ni & 1) * 2];
                    mma_bf16(acc[mi][ni], ah[mi], ph);  // hi*hi
                    mma_bf16(acc[mi][ni], ah[mi], pl);  // hi*lo
                    mma_bf16(acc[mi][ni], al[mi], ph);  // lo*hi
                }
            }
        }
        __syncthreads();
    }

    // Epilogue: acc -> C with bias
    #pragma unroll
    for (int ni = 0; ni < 4; ni++) {
        const int col = bn + wn + ni * 8 + (lane & 3) * 2;
        const float bx = bias[col];
        const float by = bias[col + 1];
        #pragma unroll
        for (int mi = 0; mi < 4; mi++) {
            const int row = bm + wm + mi * 16 + (lane >> 2);
            float* acc4 = acc[mi][ni];
            *(float2*)&C[(size_t)row * N + col] =
                make_float2(acc4[0] + bx, acc4[1] + by);
            *(float2*)&C[(size_t)(row + 8) * N + col] =
                make_float2(acc4[2] + bx, acc4[3] + by);
        }
    }
}

// ---------------------------------------------------------------------------
// Window attention: one block per (window, head).  (unchanged from R0)
// ---------------------------------------------------------------------------
__global__ void __launch_bounds__(256)
win_attn(const float* __restrict__ qkv, const float* __restrict__ bias_table,
         const int* __restrict__ rpi, float* __restrict__ out)
{
    const int b = blockIdx.x;
    const int h = blockIdx.y;
    const int tid = threadIdx.x;

    __shared__ float qs[NTOK][HD + 1];
    __shared__ float ks[NTOK][HD + 1];
    __shared__ float vs[NTOK][HD + 1];
    __shared__ float at[NTOK][NTOK + 1];

    const float scale = 0.17677669529663687f;

    for (int idx = tid; idx < NTOK * HD; idx += 256) {
        const int n = idx >> 5, d = idx & 31;
        const size_t base = ((size_t)b * NTOK + n) * QKV_N + h * HD + d;
        qs[n][d] = qkv[base] * scale;
        ks[n][d] = qkv[base + DIMC];
        vs[n][d] = qkv[base + 2 * DIMC];
    }
    __syncthreads();

    for (int idx = tid; idx < NTOK * NTOK; idx += 256) {
        const int n = idx / NTOK, m = idx - n * NTOK;
        float s = 0.f;
        #pragma unroll
        for (int d = 0; d < HD; d++) s = fmaf(qs[n][d], ks[m][d], s);
        s += bias_table[rpi[idx] * NHEADS + h];
        at[n][m] = s;
    }
    __syncthreads();

    const int warp = tid >> 5, lane = tid & 31;
    for (int n = warp; n < NTOK; n += 8) {
        float v1 = at[n][lane];
        float v2 = (lane < NTOK - 32) ? at[n][lane + 32] : -CUDART_INF_F;
        float mx = fmaxf(v1, v2);
        #pragma unroll
        for (int o = 16; o; o >>= 1) mx = fmaxf(mx, __shfl_xor_sync(0xFFFFFFFFu, mx, o));
        float e1 = __expf(v1 - mx);
        float e2 = (lane < NTOK - 32) ? __expf(v2 - mx) : 0.f;
        float sm = e1 + e2;
        #pragma unroll
        for (int o = 16; o; o >>= 1) sm += __shfl_xor_sync(0xFFFFFFFFu, sm, o);
        const float inv = __frcp_rn(sm);
        at[n][lane] = e1 * inv;
        if (lane < NTOK - 32) at[n][lane + 32] = e2 * inv;
    }
    __syncthreads();

    for (int idx = tid; idx < NTOK * HD; idx += 256) {
        const int n = idx >> 5, d = idx & 31;
        float s = 0.f;
        #pragma unroll
        for (int m = 0; m < NTOK; m++) s = fmaf(at[n][m], vs[m][d], s);
        out[((size_t)b * NTOK + n) * DIMC + h * HD + d] = s;
    }
}

// ---------------------------------------------------------------------------
extern "C" void kernel_launch(void* const* d_in, const int* in_sizes, int n_in,
                              void* d_out, int out_size)
{
    const float* x          = (const float*)d_in[0];
    const float* qkv_w      = (const float*)d_in[1];
    const float* qkv_b      = (const float*)d_in[2];
    const float* proj_w     = (const float*)d_in[3];
    const float* proj_b     = (const float*)d_in[4];
    const float* bias_table = (const float*)d_in[5];
    const int*   rpi        = (const int*)d_in[6];
    float* out = (float*)d_out;

    float* qkv = nullptr;
    float* att = nullptr;
    cudaGetSymbolAddress((void**)&qkv, g_qkv);
    cudaGetSymbolAddress((void**)&att, g_att);

    // 1) QKV GEMM: [200704, 384] x [384, 1152]
    {
        dim3 grid(QKV_N / 128, MROWS / 128);
        gemm_bf16x3<<<grid, 256>>>(x, qkv_w, qkv_b, qkv, MROWS, QKV_N, DIMC);
    }
    // 2) Window attention
    {
        dim3 grid(NWIN, NHEADS);
        win_attn<<<grid, 256>>>(qkv, bias_table, rpi, att);
    }
    // 3) Proj GEMM: [200704, 384] x [384, 384]
    {
        dim3 grid(DIMC / 128, MROWS / 128);
        gemm_bf16x3<<<grid, 256>>>(att, proj_w, proj_b, out, MROWS, DIMC, DIMC);
    }
}

// round 3
// speedup vs baseline: 2.2008x; 1.2464x over previous
#include <cuda_runtime.h>
#include <cuda_bf16.h>
#include <math_constants.h>

#define DIMC     384
#define NHEADS   12
#define HD       32
#define NTOK     49
#define NWIN     4096
#define MROWS    (NWIN * NTOK)   // 200704
#define QKV_N    (3 * DIMC)      // 1152

// Scratch (device globals — no allocation allowed)
__device__ float         g_qkv[(size_t)MROWS * QKV_N];
__device__ __nv_bfloat16 g_xh [(size_t)MROWS * DIMC];
__device__ __nv_bfloat16 g_xl [(size_t)MROWS * DIMC];
__device__ __nv_bfloat16 g_ah [(size_t)MROWS * DIMC];   // attention out hi
__device__ __nv_bfloat16 g_al [(size_t)MROWS * DIMC];   // attention out lo
__device__ __nv_bfloat16 g_qwh[(size_t)DIMC * QKV_N];
__device__ __nv_bfloat16 g_qwl[(size_t)DIMC * QKV_N];
__device__ __nv_bfloat16 g_pwh[(size_t)DIMC * DIMC];
__device__ __nv_bfloat16 g_pwl[(size_t)DIMC * DIMC];

// ---------------------------------------------------------------------------
__device__ __forceinline__ void split2(float x0, float x1,
                                       __nv_bfloat162& h, __nv_bfloat162& l) {
    __nv_bfloat16 h0 = __float2bfloat16(x0);
    __nv_bfloat16 h1 = __float2bfloat16(x1);
    __nv_bfloat16 l0 = __float2bfloat16(x0 - __bfloat162float(h0));
    __nv_bfloat16 l1 = __float2bfloat16(x1 - __bfloat162float(h1));
    h = __nv_bfloat162(h0, h1);
    l = __nv_bfloat162(l0, l1);
}

// Elementwise fp32 -> (hi, lo) bf16 split, 4 elems/thread
__global__ void __launch_bounds__(256)
split_f32(const float* __restrict__ in, __nv_bfloat16* __restrict__ hi,
          __nv_bfloat16* __restrict__ lo, size_t n4)
{
    size_t i = (size_t)blockIdx.x * blockDim.x + threadIdx.x;
    if (i >= n4) return;
    float4 v = ((const float4*)in)[i];
    __nv_bfloat162 h0, l0, h1, l1;
    split2(v.x, v.y, h0, l0);
    split2(v.z, v.w, h1, l1);
    ((__nv_bfloat162*)hi)[i * 2]     = h0;
    ((__nv_bfloat162*)hi)[i * 2 + 1] = h1;
    ((__nv_bfloat162*)lo)[i * 2]     = l0;
    ((__nv_bfloat162*)lo)[i * 2 + 1] = l1;
}

// ---------------------------------------------------------------------------
// Tensor-core GEMM, pre-split bf16 hi/lo inputs, cp.async double-buffered.
// C[M,N] = (Ah+Al)[M,K] @ (Bh+Bl)[K,N] + bias  (hh + hl + lh terms)
// BM=128, BN=128, BK=32, 256 threads (2x4 warps), warp tile 64x32.
// ---------------------------------------------------------------------------
#define AST 56     // A smem row stride (bf16): 112B, conflict-free + 16B aligned
#define BST 136    // B smem row stride (bf16): 272B, conflict-free + 16B aligned
#define SA_ELEMS (128 * AST)   // 7168
#define SB_ELEMS (32 * BST)    // 4352
#define GEMM_SMEM ((4 * SA_ELEMS + 4 * SB_ELEMS) * 2)  // 92160 bytes

__device__ __forceinline__ unsigned smem_u32(const void* p) {
    return (unsigned)__cvta_generic_to_shared(p);
}
__device__ __forceinline__ void cp16(unsigned dst, const void* src) {
    asm volatile("cp.async.cg.shared.global [%0], [%1], 16;" :: "r"(dst), "l"(src));
}
__device__ __forceinline__ void cp_commit() {
    asm volatile("cp.async.commit_group;");
}
__device__ __forceinline__ void cp_wait0() {
    asm volatile("cp.async.wait_group 0;");
}
__device__ __forceinline__ void ldsm_x4(unsigned* r, const void* p) {
    unsigned a = smem_u32(p);
    asm volatile("ldmatrix.sync.aligned.m8n8.x4.shared.b16 {%0,%1,%2,%3}, [%4];"
        : "=r"(r[0]), "=r"(r[1]), "=r"(r[2]), "=r"(r[3]) : "r"(a));
}
__device__ __forceinline__ void ldsm_x4_t(unsigned* r, const void* p) {
    unsigned a = smem_u32(p);
    asm volatile("ldmatrix.sync.aligned.m8n8.x4.trans.shared.b16 {%0,%1,%2,%3}, [%4];"
        : "=r"(r[0]), "=r"(r[1]), "=r"(r[2]), "=r"(r[3]) : "r"(a));
}
__device__ __forceinline__ void mma_bf16(float* d, const unsigned* a, const unsigned* b) {
    asm volatile(
        "mma.sync.aligned.m16n8k16.row.col.f32.bf16.bf16.f32 "
        "{%0,%1,%2,%3}, {%4,%5,%6,%7}, {%8,%9}, {%0,%1,%2,%3};"
        : "+f"(d[0]), "+f"(d[1]), "+f"(d[2]), "+f"(d[3])
        : "r"(a[0]), "r"(a[1]), "r"(a[2]), "r"(a[3]), "r"(b[0]), "r"(b[1]));
}

__global__ void __launch_bounds__(256, 2)
gemm_bf16x3(const __nv_bfloat16* __restrict__ Ah, const __nv_bfloat16* __restrict__ Al,
            const __nv_bfloat16* __restrict__ Bh, const __nv_bfloat16* __restrict__ Bl,
            const float* __restrict__ bias, float* __restrict__ C,
            int M, int N, int K)
{
    extern __shared__ __nv_bfloat16 smem[];
    __nv_bfloat16* sA = smem;                   // [stage][hi/lo][SA_ELEMS]
    __nv_bfloat16* sB = smem + 4 * SA_ELEMS;    // [stage][hi/lo][SB_ELEMS]

    const int bm = blockIdx.y * 128;
    const int bn = blockIdx.x * 128;
    const int tid  = threadIdx.x;
    const int warp = tid >> 5;
    const int lane = tid & 31;
    const int wm = (warp >> 2) * 64;
    const int wn = (warp & 3)  * 32;

    // global->smem load mapping (16B chunks)
    const int ar0 = tid >> 2;           // A row base (0..63), +64
    const int ac  = (tid & 3) * 8;      // A col (bf16)
    const int br0 = tid >> 4;           // B row base (0..15), +16
    const int bc  = (tid & 15) * 8;     // B col (bf16)

    float acc[4][4][4] = {};

    auto issue = [&](int kt, int stage) {
        __nv_bfloat16* dAh = sA + stage * 2 * SA_ELEMS;
        __nv_bfloat16* dAl = dAh + SA_ELEMS;
        #pragma unroll
        for (int rr = 0; rr < 2; rr++) {
            const int r = ar0 + rr * 64;
            const size_t g = (size_t)(bm + r) * K + kt + ac;
            cp16(smem_u32(&dAh[r * AST + ac]), Ah + g);
            cp16(smem_u32(&dAl[r * AST + ac]), Al + g);
        }
        __nv_bfloat16* dBh = sB + stage * 2 * SB_ELEMS;
        __nv_bfloat16* dBl = dBh + SB_ELEMS;
        #pragma unroll
        for (int rr = 0; rr < 2; rr++) {
            const int r = br0 + rr * 16;
            const size_t g = (size_t)(kt + r) * N + bn + bc;
            cp16(smem_u32(&dBh[r * BST + bc]), Bh + g);
            cp16(smem_u32(&dBl[r * BST + bc]), Bl + g);
        }
    };

    issue(0, 0);
    cp_commit();
    cp_wait0();
    __syncthreads();

    const int nk = K / 32;
    for (int it = 0; it < nk; it++) {
        const int cur = it & 1;
        if (it + 1 < nk) {
            issue((it + 1) * 32, cur ^ 1);
            cp_commit();
        }

        const __nv_bfloat16* pAh = sA + cur * 2 * SA_ELEMS;
        const __nv_bfloat16* pAl = pAh + SA_ELEMS;
        const __nv_bfloat16* pBh = sB + cur * 2 * SB_ELEMS;
        const __nv_bfloat16* pBl = pBh + SB_ELEMS;

        #pragma unroll
        for (int ks = 0; ks < 32; ks += 16) {
            unsigned bh[2][4], bl[2][4];
            const int bkr = ks + (lane & 15);
            #pragma unroll
            for (int nb = 0; nb < 2; nb++) {
                const int col = wn + nb * 16 + ((lane >> 4) << 3);
                ldsm_x4_t(bh[nb], &pBh[bkr * BST + col]);
                ldsm_x4_t(bl[nb], &pBl[bkr * BST + col]);
            }
            const int ar  = lane & 15;
            const int akc = ks + ((lane >> 4) << 3);
            #pragma unroll
            for (int mi = 0; mi < 4; mi++) {
                unsigned ah[4], al[4];
                const int row = wm + mi * 16 + ar;
                ldsm_x4(ah, &pAh[row * AST + akc]);
                ldsm_x4(al, &pAl[row * AST + akc]);
                #pragma unroll
                for (int ni = 0; ni < 4; ni++) {
                    const unsigned* qh = &bh[ni >> 1][(ni & 1) * 2];
                    const unsigned* ql = &bl[ni >> 1][(ni & 1) * 2];
                    mma_bf16(acc[mi][ni], ah, qh);
                    mma_bf16(acc[mi][ni], ah, ql);
                    mma_bf16(acc[mi][ni], al, qh);
                }
            }
        }

        if (it + 1 < nk) cp_wait0();
        __syncthreads();
    }

    // Epilogue
    #pragma unroll
    for (int ni = 0; ni < 4; ni++) {
        const int col = bn + wn + ni * 8 + (lane & 3) * 2;
        const float bx = bias[col];
        const float by = bias[col + 1];
        #pragma unroll
        for (int mi = 0; mi < 4; mi++) {
            const int row = bm + wm + mi * 16 + (lane >> 2);
            float* a4 = acc[mi][ni];
            *(float2*)&C[(size_t)row * N + col] =
                make_float2(a4[0] + bx, a4[1] + by);
            *(float2*)&C[(size_t)(row + 8) * N + col] =
                make_float2(a4[2] + bx, a4[3] + by);
        }
    }
}

// ---------------------------------------------------------------------------
// Window attention: one block per (window, head). Emits bf16 hi/lo.
// ---------------------------------------------------------------------------
__global__ void __launch_bounds__(256)
win_attn(const float* __restrict__ qkv, const float* __restrict__ bias_table,
         const int* __restrict__ rpi,
         __nv_bfloat16* __restrict__ outh, __nv_bfloat16* __restrict__ outl)
{
    const int b = blockIdx.x;
    const int h = blockIdx.y;
    const int tid = threadIdx.x;

    __shared__ float qs[NTOK][HD + 1];
    __shared__ float ks[NTOK][HD + 1];
    __shared__ float vs[NTOK][HD + 1];
    __shared__ float at[NTOK][NTOK + 1];

    const float scale = 0.17677669529663687f;

    for (int idx = tid; idx < NTOK * HD; idx += 256) {
        const int n = idx >> 5, d = idx & 31;
        const size_t base = ((size_t)b * NTOK + n) * QKV_N + h * HD + d;
        qs[n][d] = qkv[base] * scale;
        ks[n][d] = qkv[base + DIMC];
        vs[n][d] = qkv[base + 2 * DIMC];
    }
    __syncthreads();

    for (int idx = tid; idx < NTOK * NTOK; idx += 256) {
        const int n = idx / NTOK, m = idx - n * NTOK;
        float s = 0.f;
        #pragma unroll
        for (int d = 0; d < HD; d++) s = fmaf(qs[n][d], ks[m][d], s);
        s += bias_table[rpi[idx] * NHEADS + h];
        at[n][m] = s;
    }
    __syncthreads();

    const int warp = tid >> 5, lane = tid & 31;
    for (int n = warp; n < NTOK; n += 8) {
        float v1 = at[n][lane];
        float v2 = (lane < NTOK - 32) ? at[n][lane + 32] : -CUDART_INF_F;
        float mx = fmaxf(v1, v2);
        #pragma unroll
        for (int o = 16; o; o >>= 1) mx = fmaxf(mx, __shfl_xor_sync(0xFFFFFFFFu, mx, o));
        float e1 = __expf(v1 - mx);
        float e2 = (lane < NTOK - 32) ? __expf(v2 - mx) : 0.f;
        float sm = e1 + e2;
        #pragma unroll
        for (int o = 16; o; o >>= 1) sm += __shfl_xor_sync(0xFFFFFFFFu, sm, o);
        const float inv = __frcp_rn(sm);
        at[n][lane] = e1 * inv;
        if (lane < NTOK - 32) at[n][lane + 32] = e2 * inv;
    }
    __syncthreads();

    for (int idx = tid; idx < NTOK * HD; idx += 256) {
        const int n = idx >> 5, d = idx & 31;
        float s = 0.f;
        #pragma unroll
        for (int m = 0; m < NTOK; m++) s = fmaf(at[n][m], vs[m][d], s);
        const size_t o = ((size_t)b * NTOK + n) * DIMC + h * HD + d;
        __nv_bfloat16 hv = __float2bfloat16(s);
        outh[o] = hv;
        outl[o] = __float2bfloat16(s - __bfloat162float(hv));
    }
}

// ---------------------------------------------------------------------------
extern "C" void kernel_launch(void* const* d_in, const int* in_sizes, int n_in,
                              void* d_out, int out_size)
{
    const float* x          = (const float*)d_in[0];
    const float* qkv_w      = (const float*)d_in[1];
    const float* qkv_b      = (const float*)d_in[2];
    const float* proj_w     = (const float*)d_in[3];
    const float* proj_b     = (const float*)d_in[4];
    const float* bias_table = (const float*)d_in[5];
    const int*   rpi        = (const int*)d_in[6];
    float* out = (float*)d_out;

    float *qkv;
    __nv_bfloat16 *xh, *xl, *ah, *al, *qwh, *qwl, *pwh, *pwl;
    cudaGetSymbolAddress((void**)&qkv, g_qkv);
    cudaGetSymbolAddress((void**)&xh, g_xh);
    cudaGetSymbolAddress((void**)&xl, g_xl);
    cudaGetSymbolAddress((void**)&ah, g_ah);
    cudaGetSymbolAddress((void**)&al, g_al);
    cudaGetSymbolAddress((void**)&qwh, g_qwh);
    cudaGetSymbolAddress((void**)&qwl, g_qwl);
    cudaGetSymbolAddress((void**)&pwh, g_pwh);
    cudaGetSymbolAddress((void**)&pwl, g_pwl);

    cudaFuncSetAttribute(gemm_bf16x3,
                         cudaFuncAttributeMaxDynamicSharedMemorySize, GEMM_SMEM);

    // 0) splits
    {
        size_t n4 = (size_t)MROWS * DIMC / 4;
        split_f32<<<(unsigned)((n4 + 255) / 256), 256>>>(x, xh, xl, n4);
        size_t w4 = (size_t)DIMC * QKV_N / 4;
        split_f32<<<(unsigned)((w4 + 255) / 256), 256>>>(qkv_w, qwh, qwl, w4);
        size_t p4 = (size_t)DIMC * DIMC / 4;
        split_f32<<<(unsigned)((p4 + 255) / 256), 256>>>(proj_w, pwh, pwl, p4);
    }
    // 1) QKV GEMM: [200704,384] x [384,1152] -> fp32
    {
        dim3 grid(QKV_N / 128, MROWS / 128);
        gemm_bf16x3<<<grid, 256, GEMM_SMEM>>>(xh, xl, qwh, qwl, qkv_b, qkv,
                                              MROWS, QKV_N, DIMC);
    }
    // 2) Window attention (emits bf16 hi/lo)
    {
        dim3 grid(NWIN, NHEADS);
        win_attn<<<grid, 256>>>(qkv, bias_table, rpi, ah, al);
    }
    // 3) Proj GEMM: [200704,384] x [384,384] -> out
    {
        dim3 grid(DIMC / 128, MROWS / 128);
        gemm_bf16x3<<<grid, 256, GEMM_SMEM>>>(ah, al, pwh, pwl, proj_b, out,
                                              MROWS, DIMC, DIMC);
    }
}

// round 5
// speedup vs baseline: 2.2224x; 1.0098x over previous
#include <cuda_runtime.h>
#include <cuda_bf16.h>
#include <math_constants.h>
#include <cstdint>

#define DIMC     384
#define NHEADS   12
#define HD       32
#define NTOK     49
#define NWIN     4096
#define MROWS    (NWIN * NTOK)   // 200704
#define QKV_N    (3 * DIMC)      // 1152
#define KDIM     384

// Scratch (device globals — no allocation allowed)
__device__ float         g_qkv[(size_t)MROWS * QKV_N];
__device__ __nv_bfloat16 g_xh [(size_t)MROWS * DIMC];
__device__ __nv_bfloat16 g_xl [(size_t)MROWS * DIMC];
__device__ __nv_bfloat16 g_ah [(size_t)MROWS * DIMC];
__device__ __nv_bfloat16 g_al [(size_t)MROWS * DIMC];
__device__ __nv_bfloat16 g_qwh[(size_t)KDIM * QKV_N];
__device__ __nv_bfloat16 g_qwl[(size_t)KDIM * QKV_N];
__device__ __nv_bfloat16 g_pwh[(size_t)KDIM * DIMC];
__device__ __nv_bfloat16 g_pwl[(size_t)KDIM * DIMC];

// ---------------------------------------------------------------------------
__device__ __forceinline__ void split1(float x, __nv_bfloat16& h, __nv_bfloat16& l) {
    h = __float2bfloat16(x);
    l = __float2bfloat16(x - __bfloat162float(h));
}
__device__ __forceinline__ void split2(float x0, float x1,
                                       __nv_bfloat162& h, __nv_bfloat162& l) {
    __nv_bfloat16 h0, l0, h1, l1;
    split1(x0, h0, l0);
    split1(x1, h1, l1);
    h = __nv_bfloat162(h0, h1);
    l = __nv_bfloat162(l0, l1);
}

// Elementwise fp32 -> (hi, lo) bf16 split
__global__ void __launch_bounds__(256)
split_f32(const float* __restrict__ in, __nv_bfloat16* __restrict__ hi,
          __nv_bfloat16* __restrict__ lo, size_t n4)
{
    size_t i = (size_t)blockIdx.x * blockDim.x + threadIdx.x;
    if (i >= n4) return;
    float4 v = ((const float4*)in)[i];
    __nv_bfloat162 h0, l0, h1, l1;
    split2(v.x, v.y, h0, l0);
    split2(v.z, v.w, h1, l1);
    ((__nv_bfloat162*)hi)[i * 2]     = h0;
    ((__nv_bfloat162*)hi)[i * 2 + 1] = h1;
    ((__nv_bfloat162*)lo)[i * 2]     = l0;
    ((__nv_bfloat162*)lo)[i * 2 + 1] = l1;
}

// ---------------------------------------------------------------------------
// Tensor-core GEMM, pre-split bf16 hi/lo inputs, 3-stage cp.async pipeline.
// C[M,N] = (Ah+Al)[M,K] @ (Bh+Bl)[K,N] + bias  (hh + hl + lh terms)
// BM=128, BN=128, BK=32, 256 threads (2x4 warps), warp tile 64x32.
// ---------------------------------------------------------------------------
#define AST 40     // A smem row stride (bf16)
#define BST 136    // B smem row stride (bf16)
#define SA_ELEMS (128 * AST)                     // 5120
#define SB_ELEMS (32 * BST)                      // 4352
#define STAGE_ELEMS (2 * SA_ELEMS + 2 * SB_ELEMS)  // 18944 (37888 B)
#define NSTAGE 3
#define GEMM_SMEM (NSTAGE * STAGE_ELEMS * 2)     // 113664 bytes

__device__ __forceinline__ uint32_t smem_u32(const void* p) {
    return (uint32_t)__cvta_generic_to_shared(p);
}
__device__ __forceinline__ void cp16(uint32_t dst, const void* src) {
    asm volatile("cp.async.cg.shared.global [%0], [%1], 16;" :: "r"(dst), "l"(src));
}
__device__ __forceinline__ void cp_commit() { asm volatile("cp.async.commit_group;"); }
__device__ __forceinline__ void cp_wait0()  { asm volatile("cp.async.wait_group 0;"); }
__device__ __forceinline__ void cp_wait1()  { asm volatile("cp.async.wait_group 1;"); }

__device__ __forceinline__ void ldsm_x4(unsigned* r, const void* p) {
    unsigned a = smem_u32(p);
    asm volatile("ldmatrix.sync.aligned.m8n8.x4.shared.b16 {%0,%1,%2,%3}, [%4];"
        : "=r"(r[0]), "=r"(r[1]), "=r"(r[2]), "=r"(r[3]) : "r"(a));
}
__device__ __forceinline__ void ldsm_x4_t(unsigned* r, const void* p) {
    unsigned a = smem_u32(p);
    asm volatile("ldmatrix.sync.aligned.m8n8.x4.trans.shared.b16 {%0,%1,%2,%3}, [%4];"
        : "=r"(r[0]), "=r"(r[1]), "=r"(r[2]), "=r"(r[3]) : "r"(a));
}
__device__ __forceinline__ void mma_bf16(float* d, const unsigned* a, const unsigned* b) {
    asm volatile(
        "mma.sync.aligned.m16n8k16.row.col.f32.bf16.bf16.f32 "
        "{%0,%1,%2,%3}, {%4,%5,%6,%7}, {%8,%9}, {%0,%1,%2,%3};"
        : "+f"(d[0]), "+f"(d[1]), "+f"(d[2]), "+f"(d[3])
        : "r"(a[0]), "r"(a[1]), "r"(a[2]), "r"(a[3]), "r"(b[0]), "r"(b[1]));
}

__global__ void __launch_bounds__(256, 2)
gemm_bf16x3(const __nv_bfloat16* __restrict__ Ah, const __nv_bfloat16* __restrict__ Al,
            const __nv_bfloat16* __restrict__ Bh, const __nv_bfloat16* __restrict__ Bl,
            const float* __restrict__ bias, float* __restrict__ C,
            int M, int N, int K)
{
    extern __shared__ __nv_bfloat16 smem[];

    const int bm = blockIdx.y * 128;
    const int bn = blockIdx.x * 128;
    const int tid  = threadIdx.x;
    const int warp = tid >> 5;
    const int lane = tid & 31;
    const int wm = (warp >> 2) * 64;
    const int wn = (warp & 3)  * 32;

    // global->smem load mapping (16B chunks)
    const int ar0 = tid >> 2;           // A row base (0..63), +64
    const int ac  = (tid & 3) * 8;      // A col (bf16)
    const int br0 = tid >> 4;           // B row base (0..15), +16
    const int bc  = (tid & 15) * 8;     // B col (bf16)

    float acc[4][4][4] = {};

    auto issue = [&](int kt, int stage) {
        __nv_bfloat16* dAh = smem + stage * STAGE_ELEMS;
        __nv_bfloat16* dAl = dAh + SA_ELEMS;
        #pragma unroll
        for (int rr = 0; rr < 2; rr++) {
            const int r = ar0 + rr * 64;
            const size_t g = (size_t)(bm + r) * K + kt + ac;
            cp16(smem_u32(&dAh[r * AST + ac]), Ah + g);
            cp16(smem_u32(&dAl[r * AST + ac]), Al + g);
        }
        __nv_bfloat16* dBh = dAl + SA_ELEMS;
        __nv_bfloat16* dBl = dBh + SB_ELEMS;
        #pragma unroll
        for (int rr = 0; rr < 2; rr++) {
            const int r = br0 + rr * 16;
            const size_t g = (size_t)(kt + r) * N + bn + bc;
            cp16(smem_u32(&dBh[r * BST + bc]), Bh + g);
            cp16(smem_u32(&dBl[r * BST + bc]), Bl + g);
        }
    };

    const int nk = K / 32;   // 12
    issue(0, 0); cp_commit();
    issue(32, 1); cp_commit();

    #pragma unroll 1
    for (int it = 0; it < nk; it++) {
        const int cur = it % NSTAGE;

        if (it + 2 < nk) cp_wait1(); else cp_wait0();
        __syncthreads();
        if (it + 2 < nk) {
            issue((it + 2) * 32, (it + 2) % NSTAGE);
            cp_commit();
        }

        const __nv_bfloat16* pAh = smem + cur * STAGE_ELEMS;
        const __nv_bfloat16* pAl = pAh + SA_ELEMS;
        const __nv_bfloat16* pBh = pAl + SA_ELEMS;
        const __nv_bfloat16* pBl = pBh + SB_ELEMS;

        #pragma unroll
        for (int ks = 0; ks < 32; ks += 16) {
            unsigned af[4][4];              // holds ah, later overwritten by al
            unsigned bh[2][4], bl[2][4];
            const int ar  = lane & 15;
            const int akc = ks + ((lane >> 4) << 3);
            const int bkr = ks + (lane & 15);
            const int bcc = ((lane >> 4) << 3);

            #pragma unroll
            for (int mi = 0; mi < 4; mi++)
                ldsm_x4(af[mi], &pAh[(wm + mi * 16 + ar) * AST + akc]);
            #pragma unroll
            for (int nb = 0; nb < 2; nb++) {
                ldsm_x4_t(bh[nb], &pBh[bkr * BST + wn + nb * 16 + bcc]);
                ldsm_x4_t(bl[nb], &pBl[bkr * BST + wn + nb * 16 + bcc]);
            }
            // hh + hl
            #pragma unroll
            for (int mi = 0; mi < 4; mi++)
                #pragma unroll
                for (int ni = 0; ni < 4; ni++) {
                    mma_bf16(acc[mi][ni], af[mi], &bh[ni >> 1][(ni & 1) * 2]);
                    mma_bf16(acc[mi][ni], af[mi], &bl[ni >> 1][(ni & 1) * 2]);
                }
            // overwrite a-frags with A-lo, then lh
            #pragma unroll
            for (int mi = 0; mi < 4; mi++)
                ldsm_x4(af[mi], &pAl[(wm + mi * 16 + ar) * AST + akc]);
            #pragma unroll
            for (int mi = 0; mi < 4; mi++)
                #pragma unroll
                for (int ni = 0; ni < 4; ni++)
                    mma_bf16(acc[mi][ni], af[mi], &bh[ni >> 1][(ni & 1) * 2]);
        }
        __syncthreads();
    }

    // Epilogue
    #pragma unroll
    for (int ni = 0; ni < 4; ni++) {
        const int col = bn + wn + ni * 8 + (lane & 3) * 2;
        const float bx = bias[col];
        const float by = bias[col + 1];
        #pragma unroll
        for (int mi = 0; mi < 4; mi++) {
            const int row = bm + wm + mi * 16 + (lane >> 2);
            float* a4 = acc[mi][ni];
            *(float2*)&C[(size_t)row * N + col] =
                make_float2(a4[0] + bx, a4[1] + by);
            *(float2*)&C[(size_t)(row + 8) * N + col] =
                make_float2(a4[2] + bx, a4[3] + by);
        }
    }
}

// ---------------------------------------------------------------------------
// Window attention: one block per (window, head). Emits bf16 hi/lo.
// ---------------------------------------------------------------------------
__global__ void __launch_bounds__(256)
win_attn(const float* __restrict__ qkv, const float* __restrict__ bias_table,
         const int* __restrict__ rpi,
         __nv_bfloat16* __restrict__ outh, __nv_bfloat16* __restrict__ outl)
{
    const int b = blockIdx.x;
    const int h = blockIdx.y;
    const int tid = threadIdx.x;

    __shared__ float qs[NTOK][HD + 1];
    __shared__ float ks[NTOK][HD + 1];
    __shared__ float vs[NTOK][HD + 1];
    __shared__ float at[NTOK][NTOK + 1];

    const float scale = 0.17677669529663687f;

    for (int idx = tid; idx < NTOK * HD; idx += 256) {
        const int n = idx >> 5, d = idx & 31;
        const size_t base = ((size_t)b * NTOK + n) * QKV_N + h * HD + d;
        qs[n][d] = qkv[base] * scale;
        ks[n][d] = qkv[base + DIMC];
        vs[n][d] = qkv[base + 2 * DIMC];
    }
    __syncthreads();

    for (int idx = tid; idx < NTOK * NTOK; idx += 256) {
        const int n = idx / NTOK, m = idx - n * NTOK;
        float s = 0.f;
        #pragma unroll
        for (int d = 0; d < HD; d++) s = fmaf(qs[n][d], ks[m][d], s);
        s += bias_table[rpi[idx] * NHEADS + h];
        at[n][m] = s;
    }
    __syncthreads();

    const int warp = tid >> 5, lane = tid & 31;
    for (int n = warp; n < NTOK; n += 8) {
        float v1 = at[n][lane];
        float v2 = (lane < NTOK - 32) ? at[n][lane + 32] : -CUDART_INF_F;
        float mx = fmaxf(v1, v2);
        #pragma unroll
        for (int o = 16; o; o >>= 1) mx = fmaxf(mx, __shfl_xor_sync(0xFFFFFFFFu, mx, o));
        float e1 = __expf(v1 - mx);
        float e2 = (lane < NTOK - 32) ? __expf(v2 - mx) : 0.f;
        float sm = e1 + e2;
        #pragma unroll
        for (int o = 16; o; o >>= 1) sm += __shfl_xor_sync(0xFFFFFFFFu, sm, o);
        const float inv = __frcp_rn(sm);
        at[n][lane] = e1 * inv;
        if (lane < NTOK - 32) at[n][lane + 32] = e2 * inv;
    }
    __syncthreads();

    for (int idx = tid; idx < NTOK * HD; idx += 256) {
        const int n = idx >> 5, d = idx & 31;
        float s = 0.f;
        #pragma unroll
        for (int m = 0; m < NTOK; m++) s = fmaf(at[n][m], vs[m][d], s);
        const size_t o = ((size_t)b * NTOK + n) * DIMC + h * HD + d;
        __nv_bfloat16 hv, lv;
        split1(s, hv, lv);
        outh[o] = hv;
        outl[o] = lv;
    }
}

// ---------------------------------------------------------------------------
extern "C" void kernel_launch(void* const* d_in, const int* in_sizes, int n_in,
                              void* d_out, int out_size)
{
    const float* x          = (const float*)d_in[0];
    const float* qkv_w      = (const float*)d_in[1];
    const float* qkv_b      = (const float*)d_in[2];
    const float* proj_w     = (const float*)d_in[3];
    const float* proj_b     = (const float*)d_in[4];
    const float* bias_table = (const float*)d_in[5];
    const int*   rpi        = (const int*)d_in[6];
    float* out = (float*)d_out;

    float *qkv;
    __nv_bfloat16 *xh, *xl, *ah, *al, *qwh, *qwl, *pwh, *pwl;
    cudaGetSymbolAddress((void**)&qkv, g_qkv);
    cudaGetSymbolAddress((void**)&xh, g_xh);
    cudaGetSymbolAddress((void**)&xl, g_xl);
    cudaGetSymbolAddress((void**)&ah, g_ah);
    cudaGetSymbolAddress((void**)&al, g_al);
    cudaGetSymbolAddress((void**)&qwh, g_qwh);
    cudaGetSymbolAddress((void**)&qwl, g_qwl);
    cudaGetSymbolAddress((void**)&pwh, g_pwh);
    cudaGetSymbolAddress((void**)&pwl, g_pwl);

    cudaFuncSetAttribute(gemm_bf16x3,
                         cudaFuncAttributeMaxDynamicSharedMemorySize, GEMM_SMEM);

    // 0) splits
    {
        size_t n4 = (size_t)MROWS * DIMC / 4;
        split_f32<<<(unsigned)((n4 + 255) / 256), 256>>>(x, xh, xl, n4);
        size_t w4 = (size_t)KDIM * QKV_N / 4;
        split_f32<<<(unsigned)((w4 + 255) / 256), 256>>>(qkv_w, qwh, qwl, w4);
        size_t p4 = (size_t)KDIM * DIMC / 4;
        split_f32<<<(unsigned)((p4 + 255) / 256), 256>>>(proj_w, pwh, pwl, p4);
    }
    // 1) QKV GEMM: [200704,384] x [384,1152] -> fp32
    {
        dim3 grid(QKV_N / 128, MROWS / 128);
        gemm_bf16x3<<<grid, 256, GEMM_SMEM>>>(xh, xl, qwh, qwl, qkv_b, qkv,
                                              MROWS, QKV_N, KDIM);
    }
    // 2) Window attention (emits bf16 hi/lo)
    {
        dim3 grid(NWIN, NHEADS);
        win_attn<<<grid, 256>>>(qkv, bias_table, rpi, ah, al);
    }
    // 3) Proj GEMM: [200704,384] x [384,384] -> out
    {
        dim3 grid(DIMC / 128, MROWS / 128);
        gemm_bf16x3<<<grid, 256, GEMM_SMEM>>>(ah, al, pwh, pwl, proj_b, out,
                                              MROWS, DIMC, KDIM);
    }
}